// round 3
// baseline (speedup 1.0000x reference)
#include <cuda_runtime.h>
#include <math.h>

#define NNODES 50000
#define NEDGES 800000
#define HID    128
#define FE     16

// ---------------- scratch (static device allocations are allowed) ----------
__device__ float g_Ha[NNODES * HID];    // h @ eW1[0:128,:]
__device__ float g_Hb[NNODES * HID];    // h @ eW1[128:256,:]
__device__ float g_vec1[NNODES * 3];
__device__ float g_vec2[NNODES * 3];
__device__ int   g_rows[NEDGES];
__device__ int   g_cols[NEDGES];
__device__ int   g_is64;

// ---------------- helpers ----------------
__device__ __forceinline__ void fma4(float4& c, float s, const float4 w) {
    c.x += s * w.x; c.y += s * w.y; c.z += s * w.z; c.w += s * w.w;
}
__device__ __forceinline__ float siluf(float v) {
    return __fdividef(v, 1.0f + __expf(-v));
}
__device__ __forceinline__ float4 silu4(float4 v) {
    v.x = siluf(v.x); v.y = siluf(v.y); v.z = siluf(v.z); v.w = siluf(v.w);
    return v;
}
__device__ __forceinline__ void cpf4(float* dst, const float* src, int nfloats,
                                     int tid, int nthreads) {
    const float4* s = reinterpret_cast<const float4*>(src);
    float4* d = reinterpret_cast<float4*>(dst);
    for (int i = tid; i < nfloats / 4; i += nthreads) d[i] = s[i];
}

// ---------------- dtype detection + index canonicalization ------------------
// If edge_index is int64 (little-endian) every odd 32-bit word of the first 64
// entries is the high half of an index < 50000 => 0. If int32, those words are
// random indices; all-zero has probability ~0 (and the dataset is a fixed
// seed, so this is deterministic across calls).
__global__ void ol_detect_kernel(const int* __restrict__ ei32) {
    if (threadIdx.x == 0 && blockIdx.x == 0) {
        int any = 0;
#pragma unroll
        for (int i = 0; i < 64; i++) any |= ei32[2 * i + 1];
        g_is64 = (any == 0) ? 1 : 0;
    }
}

__global__ void ol_convert_kernel(const void* __restrict__ eiv) {
    int i = blockIdx.x * blockDim.x + threadIdx.x;
    if (i >= NEDGES) return;
    if (g_is64) {
        const long long* e = (const long long*)eiv;
        g_rows[i] = (int)e[i];
        g_cols[i] = (int)e[NEDGES + i];
    } else {
        const int* e = (const int*)eiv;
        g_rows[i] = e[i];
        g_cols[i] = e[NEDGES + i];
    }
}

// ---------------- zero vec accumulators ----------------
__global__ void ol_zero_kernel() {
    int i = blockIdx.x * blockDim.x + threadIdx.x;
    if (i < NNODES * 3) { g_vec1[i] = 0.0f; g_vec2[i] = 0.0f; }
}

// ---------------- node precompute: Ha = h@W1a, Hb = h@W1b -------------------
// block: 256 threads = 8 warps, 8 nodes per warp, weights (256x128 fp32) in smem
#define PRE_SMEM ((256 * 128 + 8 * 8 * 128) * 4)
__global__ void __launch_bounds__(256, 1)
ol_precompute_kernel(const float* __restrict__ h, const float* __restrict__ eW1) {
    extern __shared__ float smem[];
    float* Wab = smem;                   // 256*128 floats (rows 0..255 of eW1)
    float* act = smem + 256 * 128;       // 8 warps * 8 nodes * 128

    cpf4(Wab, eW1, 256 * 128, threadIdx.x, 256);
    __syncthreads();

    const int warp = threadIdx.x >> 5, lane = threadIdx.x & 31;
    float* myAct = act + warp * (8 * 128);
    float4* myAct4 = reinterpret_cast<float4*>(myAct);
    const int n0 = (blockIdx.x * 8 + warp) * 8;

    // stage 8 node rows of h
#pragma unroll
    for (int e = 0; e < 8; e++) {
        int n = n0 + e;
        float4 v = make_float4(0.f, 0.f, 0.f, 0.f);
        if (n < NNODES) v = reinterpret_cast<const float4*>(h)[n * 32 + lane];
        myAct4[e * 32 + lane] = v;
    }
    __syncwarp();

    float4 accA[8], accB[8];
#pragma unroll
    for (int e = 0; e < 8; e++) {
        accA[e] = make_float4(0.f, 0.f, 0.f, 0.f);
        accB[e] = make_float4(0.f, 0.f, 0.f, 0.f);
    }
    const float4* Wab4 = reinterpret_cast<const float4*>(Wab);
    for (int kb = 0; kb < 32; kb++) {
        float4 wa0 = Wab4[(4 * kb + 0) * 32 + lane];
        float4 wa1 = Wab4[(4 * kb + 1) * 32 + lane];
        float4 wa2 = Wab4[(4 * kb + 2) * 32 + lane];
        float4 wa3 = Wab4[(4 * kb + 3) * 32 + lane];
        float4 wb0 = Wab4[(128 + 4 * kb + 0) * 32 + lane];
        float4 wb1 = Wab4[(128 + 4 * kb + 1) * 32 + lane];
        float4 wb2 = Wab4[(128 + 4 * kb + 2) * 32 + lane];
        float4 wb3 = Wab4[(128 + 4 * kb + 3) * 32 + lane];
#pragma unroll
        for (int e = 0; e < 8; e++) {
            float4 a = myAct4[e * 32 + kb];
            fma4(accA[e], a.x, wa0); fma4(accA[e], a.y, wa1);
            fma4(accA[e], a.z, wa2); fma4(accA[e], a.w, wa3);
            fma4(accB[e], a.x, wb0); fma4(accB[e], a.y, wb1);
            fma4(accB[e], a.z, wb2); fma4(accB[e], a.w, wb3);
        }
    }
#pragma unroll
    for (int e = 0; e < 8; e++) {
        int n = n0 + e;
        if (n < NNODES) {
            reinterpret_cast<float4*>(g_Ha)[n * 32 + lane] = accA[e];
            reinterpret_cast<float4*>(g_Hb)[n * 32 + lane] = accB[e];
        }
    }
}

// ---------------- fused edge kernel ----------------
// 128 threads = 4 warps. All weights for layer-1c / layer-2 / both heads live
// in smem (loaded once; persistent CTAs). Each warp: 8 edges per batch,
// 4 dims/lane register blocking, activations via per-warp smem buffer.
#define EDGE_SMEM ((2048 + 3 * 16384 + 6 * 128 + 4 * (1024 + 128 + 16)) * 4)

__global__ void __launch_bounds__(128, 1)
ol_edge_kernel(const float* __restrict__ x,
               const float* __restrict__ edge_attr,
               const float* __restrict__ eW1, const float* __restrict__ eb1,
               const float* __restrict__ eW2, const float* __restrict__ eb2,
               const float* __restrict__ v1W1, const float* __restrict__ v1b1,
               const float* __restrict__ v1W2, const float* __restrict__ v1b2,
               const float* __restrict__ v2W1, const float* __restrict__ v2b1,
               const float* __restrict__ v2W2, const float* __restrict__ v2b2) {
    extern __shared__ float smem[];
    float* sW1c  = smem;                    // 16 x 128
    float* sW2   = sW1c + 2048;             // 128 x 128
    float* sV1   = sW2 + 16384;             // 128 x 128
    float* sV2   = sV1 + 16384;             // 128 x 128
    float* sb1   = sV2 + 16384;
    float* sb2   = sb1 + 128;
    float* sv1b1 = sb2 + 128;
    float* sv2b1 = sv1b1 + 128;
    float* sv1w2 = sv2b1 + 128;
    float* sv2w2 = sv1w2 + 128;
    float* warpbuf = sv2w2 + 128;

    const int tid = threadIdx.x;
    cpf4(sW1c, eW1 + 256 * 128, 2048, tid, 128);
    cpf4(sW2, eW2, 16384, tid, 128);
    cpf4(sV1, v1W1, 16384, tid, 128);
    cpf4(sV2, v2W1, 16384, tid, 128);
    cpf4(sb1, eb1, 128, tid, 128);
    cpf4(sb2, eb2, 128, tid, 128);
    cpf4(sv1b1, v1b1, 128, tid, 128);
    cpf4(sv2b1, v2b1, 128, tid, 128);
    cpf4(sv1w2, v1W2, 128, tid, 128);
    cpf4(sv2w2, v2W2, 128, tid, 128);
    __syncthreads();

    const float c1 = __ldg(v1b2);
    const float c2 = __ldg(v2b2);

    const int warp = tid >> 5, lane = tid & 31;
    float* act = warpbuf + warp * 1168;           // 8 * 128
    float* ea  = act + 1024;                      // 8 * 16
    float* wsc = ea + 128;                        // 8 * 2
    float4* act4 = reinterpret_cast<float4*>(act);
    const float4* ea4 = reinterpret_cast<const float4*>(ea);
    const float4* sW2_4 = reinterpret_cast<const float4*>(sW2);
    const float4* sV1_4 = reinterpret_cast<const float4*>(sV1);
    const float4* sV2_4 = reinterpret_cast<const float4*>(sV2);
    const float4* sW1c4 = reinterpret_cast<const float4*>(sW1c);

    const float4 b1v   = reinterpret_cast<const float4*>(sb1)[lane];
    const float4 b2v   = reinterpret_cast<const float4*>(sb2)[lane];
    const float4 v1b1v = reinterpret_cast<const float4*>(sv1b1)[lane];
    const float4 v2b1v = reinterpret_cast<const float4*>(sv2b1)[lane];
    const float4 w2a   = reinterpret_cast<const float4*>(sv1w2)[lane];
    const float4 w2b   = reinterpret_cast<const float4*>(sv2w2)[lane];

    const int ntiles = NEDGES / 32;
    for (int tile = blockIdx.x; tile < ntiles; tile += gridDim.x) {
        const int e0 = tile * 32 + warp * 8;

        // ---- indices (lanes 0-7 rows, 8-15 cols), broadcast via shfl ----
        int my = 0;
        if (lane < 8)       my = g_rows[e0 + lane];
        else if (lane < 16) my = g_cols[e0 + (lane - 8)];
        const int idxv = my;
        int rows[8], cols[8];
#pragma unroll
        for (int e = 0; e < 8; e++) {
            rows[e] = __shfl_sync(0xffffffffu, idxv, e);
            cols[e] = __shfl_sync(0xffffffffu, idxv, 8 + e);
        }

        // ---- stage edge_attr (8*16 contiguous floats) ----
#pragma unroll
        for (int i = 0; i < 4; i++)
            ea[i * 32 + lane] = edge_attr[e0 * 16 + i * 32 + lane];
        __syncwarp();

        // ---- layer 1: z1 = Ha[row] + Hb[col] + ea@W1c + b1 ; y1 = silu ----
#pragma unroll
        for (int e = 0; e < 8; e++) {
            float4 a = reinterpret_cast<const float4*>(g_Ha)[rows[e] * 32 + lane];
            float4 b = reinterpret_cast<const float4*>(g_Hb)[cols[e] * 32 + lane];
            float4 acc = b1v;
            acc.x += a.x + b.x; acc.y += a.y + b.y;
            acc.z += a.z + b.z; acc.w += a.w + b.w;
#pragma unroll
            for (int kk = 0; kk < 4; kk++) {
                float4 av = ea4[e * 4 + kk];
                fma4(acc, av.x, sW1c4[(4 * kk + 0) * 32 + lane]);
                fma4(acc, av.y, sW1c4[(4 * kk + 1) * 32 + lane]);
                fma4(acc, av.z, sW1c4[(4 * kk + 2) * 32 + lane]);
                fma4(acc, av.w, sW1c4[(4 * kk + 3) * 32 + lane]);
            }
            act4[e * 32 + lane] = silu4(acc);
        }
        __syncwarp();

        // ---- layer 2: ef = silu(y1 @ eW2 + b2) ----
        {
            float4 acc2[8];
#pragma unroll
            for (int e = 0; e < 8; e++) acc2[e] = b2v;
            for (int kb = 0; kb < 32; kb++) {
                float4 w0 = sW2_4[(4 * kb + 0) * 32 + lane];
                float4 w1 = sW2_4[(4 * kb + 1) * 32 + lane];
                float4 w2 = sW2_4[(4 * kb + 2) * 32 + lane];
                float4 w3 = sW2_4[(4 * kb + 3) * 32 + lane];
#pragma unroll
                for (int e = 0; e < 8; e++) {
                    float4 a = act4[e * 32 + kb];
                    fma4(acc2[e], a.x, w0); fma4(acc2[e], a.y, w1);
                    fma4(acc2[e], a.z, w2); fma4(acc2[e], a.w, w3);
                }
            }
            __syncwarp();   // everyone done reading y1
#pragma unroll
            for (int e = 0; e < 8; e++) act4[e * 32 + lane] = silu4(acc2[e]);
            __syncwarp();
        }

        // ---- head 1: w1 = silu(ef@v1W1+v1b1) . v1W2 + v1b2 ----
        {
            float4 accu[8];
#pragma unroll
            for (int e = 0; e < 8; e++) accu[e] = v1b1v;
            for (int kb = 0; kb < 32; kb++) {
                float4 w0 = sV1_4[(4 * kb + 0) * 32 + lane];
                float4 w1 = sV1_4[(4 * kb + 1) * 32 + lane];
                float4 w2 = sV1_4[(4 * kb + 2) * 32 + lane];
                float4 w3 = sV1_4[(4 * kb + 3) * 32 + lane];
#pragma unroll
                for (int e = 0; e < 8; e++) {
                    float4 a = act4[e * 32 + kb];
                    fma4(accu[e], a.x, w0); fma4(accu[e], a.y, w1);
                    fma4(accu[e], a.z, w2); fma4(accu[e], a.w, w3);
                }
            }
#pragma unroll
            for (int e = 0; e < 8; e++) {
                float4 u = silu4(accu[e]);
                float p = u.x * w2a.x + u.y * w2a.y + u.z * w2a.z + u.w * w2a.w;
#pragma unroll
                for (int off = 16; off; off >>= 1)
                    p += __shfl_xor_sync(0xffffffffu, p, off);
                if (lane == 0) wsc[2 * e] = p + c1;
            }
        }
        // ---- head 2 ----
        {
            float4 accu[8];
#pragma unroll
            for (int e = 0; e < 8; e++) accu[e] = v2b1v;
            for (int kb = 0; kb < 32; kb++) {
                float4 w0 = sV2_4[(4 * kb + 0) * 32 + lane];
                float4 w1 = sV2_4[(4 * kb + 1) * 32 + lane];
                float4 w2 = sV2_4[(4 * kb + 2) * 32 + lane];
                float4 w3 = sV2_4[(4 * kb + 3) * 32 + lane];
#pragma unroll
                for (int e = 0; e < 8; e++) {
                    float4 a = act4[e * 32 + kb];
                    fma4(accu[e], a.x, w0); fma4(accu[e], a.y, w1);
                    fma4(accu[e], a.z, w2); fma4(accu[e], a.w, w3);
                }
            }
#pragma unroll
            for (int e = 0; e < 8; e++) {
                float4 u = silu4(accu[e]);
                float p = u.x * w2b.x + u.y * w2b.y + u.z * w2b.z + u.w * w2b.w;
#pragma unroll
                for (int off = 16; off; off >>= 1)
                    p += __shfl_xor_sync(0xffffffffu, p, off);
                if (lane == 0) wsc[2 * e + 1] = p + c2;
            }
        }
        __syncwarp();

        // ---- scatter: lanes 0..23 -> (edge e = lane/3, component d = lane%3)
        {
            int e = lane / 3;
            int d = lane - 3 * e;
            int r = __shfl_sync(0xffffffffu, idxv, (e < 8) ? e : 0);
            int c = __shfl_sync(0xffffffffu, idxv, (e < 8) ? (8 + e) : 8);
            if (lane < 24) {
                float rp = x[c * 3 + d] - x[r * 3 + d];
                atomicAdd(&g_vec1[r * 3 + d], rp * wsc[2 * e]);
                atomicAdd(&g_vec2[r * 3 + d], rp * wsc[2 * e + 1]);
            }
        }
        __syncwarp();
    }
}

// ---------------- finalize: Gram-Schmidt per node ----------------
__global__ void ol_finalize_kernel(float* __restrict__ out) {
    int n = blockIdx.x * blockDim.x + threadIdx.x;
    if (n >= NNODES) return;
    float v1x = g_vec1[n * 3 + 0], v1y = g_vec1[n * 3 + 1], v1z = g_vec1[n * 3 + 2];
    float v2x = g_vec2[n * 3 + 0], v2y = g_vec2[n * 3 + 1], v2z = g_vec2[n * 3 + 2];

    float n1 = fmaxf(sqrtf(v1x * v1x + v1y * v1y + v1z * v1z), 1e-12f);
    float e1x = v1x / n1, e1y = v1y / n1, e1z = v1z / n1;

    float dp = e1x * v2x + e1y * v2y + e1z * v2z;
    float px = v2x - dp * e1x, py = v2y - dp * e1y, pz = v2z - dp * e1z;
    float n2 = fmaxf(sqrtf(px * px + py * py + pz * pz), 1e-12f);
    float e2x = px / n2, e2y = py / n2, e2z = pz / n2;

    float e3x = e1y * e2z - e1z * e2y;
    float e3y = e1z * e2x - e1x * e2z;
    float e3z = e1x * e2y - e1y * e2x;

    float* o = out + n * 9;     // out[n, i, j] = (e_j)[i]
    o[0] = e1x; o[1] = e2x; o[2] = e3x;
    o[3] = e1y; o[4] = e2y; o[5] = e3y;
    o[6] = e1z; o[7] = e2z; o[8] = e3z;
}

// ---------------- launch ----------------
extern "C" void kernel_launch(void* const* d_in, const int* in_sizes, int n_in,
                              void* d_out, int out_size) {
    const float* h         = (const float*)d_in[0];
    const float* x         = (const float*)d_in[1];
    const void*  ei        = d_in[2];
    const float* edge_attr = (const float*)d_in[3];
    const float* eW1 = (const float*)d_in[4];  const float* eb1 = (const float*)d_in[5];
    const float* eW2 = (const float*)d_in[6];  const float* eb2 = (const float*)d_in[7];
    const float* v1W1 = (const float*)d_in[8]; const float* v1b1 = (const float*)d_in[9];
    const float* v1W2 = (const float*)d_in[10]; const float* v1b2 = (const float*)d_in[11];
    const float* v2W1 = (const float*)d_in[12]; const float* v2b1 = (const float*)d_in[13];
    const float* v2W2 = (const float*)d_in[14]; const float* v2b2 = (const float*)d_in[15];
    float* out = (float*)d_out;

    cudaFuncSetAttribute(ol_precompute_kernel,
                         cudaFuncAttributeMaxDynamicSharedMemorySize, PRE_SMEM);
    cudaFuncSetAttribute(ol_edge_kernel,
                         cudaFuncAttributeMaxDynamicSharedMemorySize, EDGE_SMEM);

    ol_detect_kernel<<<1, 32>>>((const int*)ei);
    ol_convert_kernel<<<(NEDGES + 255) / 256, 256>>>(ei);
    ol_zero_kernel<<<(NNODES * 3 + 255) / 256, 256>>>();
    ol_precompute_kernel<<<(NNODES + 63) / 64, 256, PRE_SMEM>>>(h, eW1);
    ol_edge_kernel<<<148, 128, EDGE_SMEM>>>(x, edge_attr,
                                            eW1, eb1, eW2, eb2,
                                            v1W1, v1b1, v1W2, v1b2,
                                            v2W1, v2b1, v2W2, v2b2);
    ol_finalize_kernel<<<(NNODES + 255) / 256, 256>>>(out);
}

// round 4
// speedup vs baseline: 1.2736x; 1.2736x over previous
#include <cuda_runtime.h>
#include <math.h>

#define NNODES 50000
#define NEDGES 800000
#define HID    128
#define FE     16

typedef unsigned long long u64;

// ---------------- scratch ----------------
__device__ float g_Ha[NNODES * HID];    // h @ eW1[0:128,:]
__device__ float g_Hb[NNODES * HID];    // h @ eW1[128:256,:]
__device__ float g_vec1[NNODES * 3];
__device__ float g_vec2[NNODES * 3];
__device__ int   g_rows[NEDGES];
__device__ int   g_cols[NEDGES];
__device__ int   g_is64;

// ---------------- f32x2 helpers (FFMA2 path; PTX-only) ----------------
__device__ __forceinline__ u64 dup2(float s) {
    u64 r; asm("mov.b64 %0, {%1, %1};" : "=l"(r) : "f"(s)); return r;
}
__device__ __forceinline__ u64 pack2(float lo, float hi) {
    u64 r; asm("mov.b64 %0, {%1, %2};" : "=l"(r) : "f"(lo), "f"(hi)); return r;
}
__device__ __forceinline__ float2 unpack2(u64 v) {
    float2 f; asm("mov.b64 {%0, %1}, %2;" : "=f"(f.x), "=f"(f.y) : "l"(v)); return f;
}
__device__ __forceinline__ void fma2(u64& c, u64 a, u64 b) {
    asm("fma.rn.f32x2 %0, %1, %2, %3;" : "=l"(c) : "l"(a), "l"(b), "l"(c));
}
__device__ __forceinline__ void add2(u64& c, u64 a) {
    asm("add.rn.f32x2 %0, %1, %2;" : "=l"(c) : "l"(a), "l"(c));
}

__device__ __forceinline__ float siluf(float v) {
    return __fdividef(v, 1.0f + __expf(-v));
}
__device__ __forceinline__ void cpf4(float* dst, const float* src, int nfloats,
                                     int tid, int nthreads) {
    const float4* s = reinterpret_cast<const float4*>(src);
    float4* d = reinterpret_cast<float4*>(dst);
    for (int i = tid; i < nfloats / 4; i += nthreads) d[i] = s[i];
}

// ---------------- dtype detection + index canonicalization ------------------
__global__ void ol_detect_kernel(const int* __restrict__ ei32) {
    if (threadIdx.x == 0 && blockIdx.x == 0) {
        int any = 0;
#pragma unroll
        for (int i = 0; i < 64; i++) any |= ei32[2 * i + 1];
        g_is64 = (any == 0) ? 1 : 0;
    }
}

__global__ void ol_convert_kernel(const void* __restrict__ eiv) {
    int i = blockIdx.x * blockDim.x + threadIdx.x;
    if (i >= NEDGES) return;
    if (g_is64) {
        const long long* e = (const long long*)eiv;
        g_rows[i] = (int)e[i];
        g_cols[i] = (int)e[NEDGES + i];
    } else {
        const int* e = (const int*)eiv;
        g_rows[i] = e[i];
        g_cols[i] = e[NEDGES + i];
    }
}

// ---------------- zero vec accumulators ----------------
__global__ void ol_zero_kernel() {
    int i = blockIdx.x * blockDim.x + threadIdx.x;
    if (i < NNODES * 3) { g_vec1[i] = 0.0f; g_vec2[i] = 0.0f; }
}

// ---------------- node precompute: Ha = h@W1a, Hb = h@W1b (f32x2) ----------
#define PRE_SMEM ((256 * 128 + 8 * 8 * 128) * 4)
__global__ void __launch_bounds__(256, 1)
ol_precompute_kernel(const float* __restrict__ h, const float* __restrict__ eW1) {
    extern __shared__ float smem[];
    float* Wab = smem;                   // 256*128 floats (rows 0..255 of eW1)
    float* act = smem + 256 * 128;       // 8 warps * 8 nodes * 128

    cpf4(Wab, eW1, 256 * 128, threadIdx.x, 256);
    __syncthreads();

    const int warp = threadIdx.x >> 5, lane = threadIdx.x & 31;
    float* myAct = act + warp * (8 * 128);
    float4* myAct4 = reinterpret_cast<float4*>(myAct);
    const int n0 = (blockIdx.x * 8 + warp) * 8;

#pragma unroll
    for (int e = 0; e < 8; e++) {
        int n = n0 + e;
        float4 v = make_float4(0.f, 0.f, 0.f, 0.f);
        if (n < NNODES) v = reinterpret_cast<const float4*>(h)[n * 32 + lane];
        myAct4[e * 32 + lane] = v;
    }
    __syncwarp();

    u64 accA0[8], accA1[8], accB0[8], accB1[8];
#pragma unroll
    for (int e = 0; e < 8; e++) {
        accA0[e] = 0ull; accA1[e] = 0ull; accB0[e] = 0ull; accB1[e] = 0ull;
    }
    const ulonglong2* Wab2 = reinterpret_cast<const ulonglong2*>(Wab);
    for (int kb = 0; kb < 32; kb++) {
        ulonglong2 wa0 = Wab2[(4 * kb + 0) * 32 + lane];
        ulonglong2 wa1 = Wab2[(4 * kb + 1) * 32 + lane];
        ulonglong2 wa2 = Wab2[(4 * kb + 2) * 32 + lane];
        ulonglong2 wa3 = Wab2[(4 * kb + 3) * 32 + lane];
        ulonglong2 wb0 = Wab2[(128 + 4 * kb + 0) * 32 + lane];
        ulonglong2 wb1 = Wab2[(128 + 4 * kb + 1) * 32 + lane];
        ulonglong2 wb2 = Wab2[(128 + 4 * kb + 2) * 32 + lane];
        ulonglong2 wb3 = Wab2[(128 + 4 * kb + 3) * 32 + lane];
#pragma unroll
        for (int e = 0; e < 8; e++) {
            float4 a = myAct4[e * 32 + kb];
            u64 dx = dup2(a.x), dy = dup2(a.y), dz = dup2(a.z), dw = dup2(a.w);
            fma2(accA0[e], dx, wa0.x); fma2(accA1[e], dx, wa0.y);
            fma2(accA0[e], dy, wa1.x); fma2(accA1[e], dy, wa1.y);
            fma2(accA0[e], dz, wa2.x); fma2(accA1[e], dz, wa2.y);
            fma2(accA0[e], dw, wa3.x); fma2(accA1[e], dw, wa3.y);
            fma2(accB0[e], dx, wb0.x); fma2(accB1[e], dx, wb0.y);
            fma2(accB0[e], dy, wb1.x); fma2(accB1[e], dy, wb1.y);
            fma2(accB0[e], dz, wb2.x); fma2(accB1[e], dz, wb2.y);
            fma2(accB0[e], dw, wb3.x); fma2(accB1[e], dw, wb3.y);
        }
    }
#pragma unroll
    for (int e = 0; e < 8; e++) {
        int n = n0 + e;
        if (n < NNODES) {
            reinterpret_cast<ulonglong2*>(g_Ha)[n * 32 + lane] =
                make_ulonglong2(accA0[e], accA1[e]);
            reinterpret_cast<ulonglong2*>(g_Hb)[n * 32 + lane] =
                make_ulonglong2(accB0[e], accB1[e]);
        }
    }
}

// ---------------- fused edge kernel (f32x2, 256 thr, 4 edges/warp) ----------
// smem floats: W1c 2048 | eW2 16384 | v1W1 16384 | v2W1 16384 | 6*128 vectors |
//              8 warps * (act 512 + ea 64 + wsc 8)
#define EDGE_SMEM ((2048 + 3 * 16384 + 6 * 128 + 8 * 584) * 4)

__global__ void __launch_bounds__(256, 1)
ol_edge_kernel(const float* __restrict__ x,
               const float* __restrict__ edge_attr,
               const float* __restrict__ eW1, const float* __restrict__ eb1,
               const float* __restrict__ eW2, const float* __restrict__ eb2,
               const float* __restrict__ v1W1, const float* __restrict__ v1b1,
               const float* __restrict__ v1W2, const float* __restrict__ v1b2,
               const float* __restrict__ v2W1, const float* __restrict__ v2b1,
               const float* __restrict__ v2W2, const float* __restrict__ v2b2) {
    extern __shared__ float smem[];
    float* sW1c  = smem;                    // 16 x 128
    float* sW2   = sW1c + 2048;             // 128 x 128
    float* sV1   = sW2 + 16384;             // 128 x 128
    float* sV2   = sV1 + 16384;             // 128 x 128
    float* sb1   = sV2 + 16384;
    float* sb2   = sb1 + 128;
    float* sv1b1 = sb2 + 128;
    float* sv2b1 = sv1b1 + 128;
    float* sv1w2 = sv2b1 + 128;
    float* sv2w2 = sv1w2 + 128;
    float* warpbuf = sv2w2 + 128;

    const int tid = threadIdx.x;
    cpf4(sW1c, eW1 + 256 * 128, 2048, tid, 256);
    cpf4(sW2, eW2, 16384, tid, 256);
    cpf4(sV1, v1W1, 16384, tid, 256);
    cpf4(sV2, v2W1, 16384, tid, 256);
    cpf4(sb1, eb1, 128, tid, 256);
    cpf4(sb2, eb2, 128, tid, 256);
    cpf4(sv1b1, v1b1, 128, tid, 256);
    cpf4(sv2b1, v2b1, 128, tid, 256);
    cpf4(sv1w2, v1W2, 128, tid, 256);
    cpf4(sv2w2, v2W2, 128, tid, 256);
    __syncthreads();

    const float c1 = __ldg(v1b2);
    const float c2 = __ldg(v2b2);

    const int warp = tid >> 5, lane = tid & 31;
    float* act = warpbuf + warp * 584;            // 4 * 128
    float* ea  = act + 512;                       // 4 * 16
    float* wsc = ea + 64;                         // 4 * 2
    float4* act4 = reinterpret_cast<float4*>(act);
    const float4* ea4 = reinterpret_cast<const float4*>(ea);
    const ulonglong2* sW2_u = reinterpret_cast<const ulonglong2*>(sW2);
    const ulonglong2* sV1_u = reinterpret_cast<const ulonglong2*>(sV1);
    const ulonglong2* sV2_u = reinterpret_cast<const ulonglong2*>(sV2);
    const ulonglong2* sW1c_u = reinterpret_cast<const ulonglong2*>(sW1c);

    const float4 b1v   = reinterpret_cast<const float4*>(sb1)[lane];
    const float4 b2v   = reinterpret_cast<const float4*>(sb2)[lane];
    const float4 v1b1v = reinterpret_cast<const float4*>(sv1b1)[lane];
    const float4 v2b1v = reinterpret_cast<const float4*>(sv2b1)[lane];
    const float4 w2a   = reinterpret_cast<const float4*>(sv1w2)[lane];
    const float4 w2b   = reinterpret_cast<const float4*>(sv2w2)[lane];

    const u64 b1lo = pack2(b1v.x, b1v.y),     b1hi = pack2(b1v.z, b1v.w);
    const u64 b2lo = pack2(b2v.x, b2v.y),     b2hi = pack2(b2v.z, b2v.w);
    const u64 h1lo = pack2(v1b1v.x, v1b1v.y), h1hi = pack2(v1b1v.z, v1b1v.w);
    const u64 h2lo = pack2(v2b1v.x, v2b1v.y), h2hi = pack2(v2b1v.z, v2b1v.w);

    const int ntiles = NEDGES / 32;
    for (int tile = blockIdx.x; tile < ntiles; tile += gridDim.x) {
        const int e0 = tile * 32 + warp * 4;

        // ---- indices (lanes 0-3 rows, 4-7 cols), broadcast via shfl ----
        int my = 0;
        if (lane < 4)      my = g_rows[e0 + lane];
        else if (lane < 8) my = g_cols[e0 + (lane - 4)];
        const int idxv = my;
        int rows[4], cols[4];
#pragma unroll
        for (int e = 0; e < 4; e++) {
            rows[e] = __shfl_sync(0xffffffffu, idxv, e);
            cols[e] = __shfl_sync(0xffffffffu, idxv, 4 + e);
        }

        // ---- stage edge_attr (4*16 = 64 contiguous floats) ----
#pragma unroll
        for (int i = 0; i < 2; i++)
            ea[i * 32 + lane] = edge_attr[e0 * 16 + i * 32 + lane];
        __syncwarp();

        // ---- layer 1: z1 = Ha[row] + Hb[col] + ea@W1c + b1 ; y1 = silu ----
#pragma unroll
        for (int e = 0; e < 4; e++) {
            ulonglong2 a = reinterpret_cast<const ulonglong2*>(g_Ha)[rows[e] * 32 + lane];
            ulonglong2 b = reinterpret_cast<const ulonglong2*>(g_Hb)[cols[e] * 32 + lane];
            u64 acc0 = b1lo, acc1 = b1hi;
            add2(acc0, a.x); add2(acc0, b.x);
            add2(acc1, a.y); add2(acc1, b.y);
#pragma unroll
            for (int kk = 0; kk < 4; kk++) {
                float4 av = ea4[e * 4 + kk];
                ulonglong2 w0 = sW1c_u[(4 * kk + 0) * 32 + lane];
                ulonglong2 w1 = sW1c_u[(4 * kk + 1) * 32 + lane];
                ulonglong2 w2 = sW1c_u[(4 * kk + 2) * 32 + lane];
                ulonglong2 w3 = sW1c_u[(4 * kk + 3) * 32 + lane];
                u64 dx = dup2(av.x), dy = dup2(av.y), dz = dup2(av.z), dw = dup2(av.w);
                fma2(acc0, dx, w0.x); fma2(acc1, dx, w0.y);
                fma2(acc0, dy, w1.x); fma2(acc1, dy, w1.y);
                fma2(acc0, dz, w2.x); fma2(acc1, dz, w2.y);
                fma2(acc0, dw, w3.x); fma2(acc1, dw, w3.y);
            }
            float2 lo = unpack2(acc0), hi = unpack2(acc1);
            act4[e * 32 + lane] = make_float4(siluf(lo.x), siluf(lo.y),
                                              siluf(hi.x), siluf(hi.y));
        }
        __syncwarp();

        // ---- layer 2: ef = silu(y1 @ eW2 + b2) ----
        {
            u64 acc0[4], acc1[4];
#pragma unroll
            for (int e = 0; e < 4; e++) { acc0[e] = b2lo; acc1[e] = b2hi; }
            for (int kb = 0; kb < 32; kb++) {
                ulonglong2 w0 = sW2_u[(4 * kb + 0) * 32 + lane];
                ulonglong2 w1 = sW2_u[(4 * kb + 1) * 32 + lane];
                ulonglong2 w2 = sW2_u[(4 * kb + 2) * 32 + lane];
                ulonglong2 w3 = sW2_u[(4 * kb + 3) * 32 + lane];
#pragma unroll
                for (int e = 0; e < 4; e++) {
                    float4 a = act4[e * 32 + kb];
                    u64 dx = dup2(a.x), dy = dup2(a.y), dz = dup2(a.z), dw = dup2(a.w);
                    fma2(acc0[e], dx, w0.x); fma2(acc1[e], dx, w0.y);
                    fma2(acc0[e], dy, w1.x); fma2(acc1[e], dy, w1.y);
                    fma2(acc0[e], dz, w2.x); fma2(acc1[e], dz, w2.y);
                    fma2(acc0[e], dw, w3.x); fma2(acc1[e], dw, w3.y);
                }
            }
            __syncwarp();   // everyone done reading y1
#pragma unroll
            for (int e = 0; e < 4; e++) {
                float2 lo = unpack2(acc0[e]), hi = unpack2(acc1[e]);
                act4[e * 32 + lane] = make_float4(siluf(lo.x), siluf(lo.y),
                                                  siluf(hi.x), siluf(hi.y));
            }
            __syncwarp();
        }

        // ---- heads fused: u1 = silu(ef@v1W1+v1b1), u2 = silu(ef@v2W1+v2b1) ----
        {
            u64 a10[4], a11[4], a20[4], a21[4];
#pragma unroll
            for (int e = 0; e < 4; e++) {
                a10[e] = h1lo; a11[e] = h1hi; a20[e] = h2lo; a21[e] = h2hi;
            }
            for (int kb = 0; kb < 32; kb++) {
                ulonglong2 p0 = sV1_u[(4 * kb + 0) * 32 + lane];
                ulonglong2 p1 = sV1_u[(4 * kb + 1) * 32 + lane];
                ulonglong2 p2 = sV1_u[(4 * kb + 2) * 32 + lane];
                ulonglong2 p3 = sV1_u[(4 * kb + 3) * 32 + lane];
                ulonglong2 q0 = sV2_u[(4 * kb + 0) * 32 + lane];
                ulonglong2 q1 = sV2_u[(4 * kb + 1) * 32 + lane];
                ulonglong2 q2 = sV2_u[(4 * kb + 2) * 32 + lane];
                ulonglong2 q3 = sV2_u[(4 * kb + 3) * 32 + lane];
#pragma unroll
                for (int e = 0; e < 4; e++) {
                    float4 a = act4[e * 32 + kb];
                    u64 dx = dup2(a.x), dy = dup2(a.y), dz = dup2(a.z), dw = dup2(a.w);
                    fma2(a10[e], dx, p0.x); fma2(a11[e], dx, p0.y);
                    fma2(a10[e], dy, p1.x); fma2(a11[e], dy, p1.y);
                    fma2(a10[e], dz, p2.x); fma2(a11[e], dz, p2.y);
                    fma2(a10[e], dw, p3.x); fma2(a11[e], dw, p3.y);
                    fma2(a20[e], dx, q0.x); fma2(a21[e], dx, q0.y);
                    fma2(a20[e], dy, q1.x); fma2(a21[e], dy, q1.y);
                    fma2(a20[e], dz, q2.x); fma2(a21[e], dz, q2.y);
                    fma2(a20[e], dw, q3.x); fma2(a21[e], dw, q3.y);
                }
            }
#pragma unroll
            for (int e = 0; e < 4; e++) {
                float2 lo = unpack2(a10[e]), hi = unpack2(a11[e]);
                float p = siluf(lo.x) * w2a.x + siluf(lo.y) * w2a.y
                        + siluf(hi.x) * w2a.z + siluf(hi.y) * w2a.w;
                float2 lo2 = unpack2(a20[e]), hi2 = unpack2(a21[e]);
                float q = siluf(lo2.x) * w2b.x + siluf(lo2.y) * w2b.y
                        + siluf(hi2.x) * w2b.z + siluf(hi2.y) * w2b.w;
#pragma unroll
                for (int off = 16; off; off >>= 1) {
                    p += __shfl_xor_sync(0xffffffffu, p, off);
                    q += __shfl_xor_sync(0xffffffffu, q, off);
                }
                if (lane == 0) { wsc[2 * e] = p + c1; wsc[2 * e + 1] = q + c2; }
            }
        }
        __syncwarp();

        // ---- scatter: lanes 0..11 -> (edge e = lane/3, component d = lane%3)
        {
            int e = lane / 3;
            int d = lane - 3 * e;
            int r = __shfl_sync(0xffffffffu, idxv, (e < 4) ? e : 0);
            int c = __shfl_sync(0xffffffffu, idxv, (e < 4) ? (4 + e) : 4);
            if (lane < 12) {
                float rp = x[c * 3 + d] - x[r * 3 + d];
                atomicAdd(&g_vec1[r * 3 + d], rp * wsc[2 * e]);
                atomicAdd(&g_vec2[r * 3 + d], rp * wsc[2 * e + 1]);
            }
        }
        __syncwarp();
    }
}

// ---------------- finalize: Gram-Schmidt per node ----------------
__global__ void ol_finalize_kernel(float* __restrict__ out) {
    int n = blockIdx.x * blockDim.x + threadIdx.x;
    if (n >= NNODES) return;
    float v1x = g_vec1[n * 3 + 0], v1y = g_vec1[n * 3 + 1], v1z = g_vec1[n * 3 + 2];
    float v2x = g_vec2[n * 3 + 0], v2y = g_vec2[n * 3 + 1], v2z = g_vec2[n * 3 + 2];

    float n1 = fmaxf(sqrtf(v1x * v1x + v1y * v1y + v1z * v1z), 1e-12f);
    float e1x = v1x / n1, e1y = v1y / n1, e1z = v1z / n1;

    float dp = e1x * v2x + e1y * v2y + e1z * v2z;
    float px = v2x - dp * e1x, py = v2y - dp * e1y, pz = v2z - dp * e1z;
    float n2 = fmaxf(sqrtf(px * px + py * py + pz * pz), 1e-12f);
    float e2x = px / n2, e2y = py / n2, e2z = pz / n2;

    float e3x = e1y * e2z - e1z * e2y;
    float e3y = e1z * e2x - e1x * e2z;
    float e3z = e1x * e2y - e1y * e2x;

    float* o = out + n * 9;     // out[n, i, j] = (e_j)[i]
    o[0] = e1x; o[1] = e2x; o[2] = e3x;
    o[3] = e1y; o[4] = e2y; o[5] = e3y;
    o[6] = e1z; o[7] = e2z; o[8] = e3z;
}

// ---------------- launch ----------------
extern "C" void kernel_launch(void* const* d_in, const int* in_sizes, int n_in,
                              void* d_out, int out_size) {
    const float* h         = (const float*)d_in[0];
    const float* x         = (const float*)d_in[1];
    const void*  ei        = d_in[2];
    const float* edge_attr = (const float*)d_in[3];
    const float* eW1 = (const float*)d_in[4];  const float* eb1 = (const float*)d_in[5];
    const float* eW2 = (const float*)d_in[6];  const float* eb2 = (const float*)d_in[7];
    const float* v1W1 = (const float*)d_in[8]; const float* v1b1 = (const float*)d_in[9];
    const float* v1W2 = (const float*)d_in[10]; const float* v1b2 = (const float*)d_in[11];
    const float* v2W1 = (const float*)d_in[12]; const float* v2b1 = (const float*)d_in[13];
    const float* v2W2 = (const float*)d_in[14]; const float* v2b2 = (const float*)d_in[15];
    float* out = (float*)d_out;

    cudaFuncSetAttribute(ol_precompute_kernel,
                         cudaFuncAttributeMaxDynamicSharedMemorySize, PRE_SMEM);
    cudaFuncSetAttribute(ol_edge_kernel,
                         cudaFuncAttributeMaxDynamicSharedMemorySize, EDGE_SMEM);

    ol_detect_kernel<<<1, 32>>>((const int*)ei);
    ol_convert_kernel<<<(NEDGES + 255) / 256, 256>>>(ei);
    ol_zero_kernel<<<(NNODES * 3 + 255) / 256, 256>>>();
    ol_precompute_kernel<<<(NNODES + 63) / 64, 256, PRE_SMEM>>>(h, eW1);
    ol_edge_kernel<<<148, 256, EDGE_SMEM>>>(x, edge_attr,
                                            eW1, eb1, eW2, eb2,
                                            v1W1, v1b1, v1W2, v1b2,
                                            v2W1, v2b1, v2W2, v2b2);
    ol_finalize_kernel<<<(NNODES + 255) / 256, 256>>>(out);
}